// round 15
// baseline (speedup 1.0000x reference)
#include <cuda_runtime.h>
#include <cstdint>
#include <math.h>

// ---------------- problem constants ----------------
#define BB   16
#define NA   512
#define LA   1024
#define CD   128
#define GD   64
#define NH   4
#define LATD 128
#define BN   (BB*NA)
#define LOG2E 1.4426950408889634f

// ---------------- device scratch ----------------
__device__ float    g_wcat [CD*NH*GD];     // pre-rounded tf32
__device__ float    g_wgo  [NH*GD*CD];     // pre-rounded W_go copy
__device__ float    g_eat  [100*CD];       // pre-rounded E_atom
__device__ float    g_wh   [BN*NH*GD];
__device__ float    g_src1 [NH*BN];        // pre-scaled by log2e
__device__ float    g_dst1 [NH*BN];
__device__ float    g_multi[BN*NH*GD];
__device__ float    g_wh2  [BN*CD];
__device__ float    g_src2 [BN];
__device__ float    g_dst2 [BN];
__device__ float    g_x    [BN*CD];
__device__ float    g_wcT  [CD*LATD];
__device__ float    g_waT  [LATD*LATD];
__device__ float    g_avec [BN*LATD];
__device__ float    g_pv0  [BB*LA*CD];
__device__ float    g_pv1  [BB*LA*CD];
__device__ float    g_comp [BB*LATD];
__device__ float    g_prot [BB*LATD];
__device__ unsigned g_adjbits[BN*16];

__device__ __forceinline__ float lrelu_f(float x){ return x > 0.f ? x : 0.2f*x; }
__device__ __forceinline__ float elu_f(float x){ return x > 0.f ? x : (__expf(x) - 1.f); }

__device__ __forceinline__ uint32_t to_tf32(float f){
    uint32_t u; asm("cvt.rna.tf32.f32 %0, %1;" : "=r"(u) : "f"(f)); return u;
}
__device__ __forceinline__ float round_tf32(float f){ return __uint_as_float(to_tf32(f)); }
__device__ __forceinline__ void mma_tf32(float* d,
    uint32_t a0, uint32_t a1, uint32_t a2, uint32_t a3, uint32_t b0, uint32_t b1){
    asm volatile("mma.sync.aligned.m16n8k8.row.col.f32.tf32.tf32.f32 "
        "{%0,%1,%2,%3}, {%4,%5,%6,%7}, {%8,%9}, {%0,%1,%2,%3};"
        : "+f"(d[0]), "+f"(d[1]), "+f"(d[2]), "+f"(d[3])
        : "r"(a0), "r"(a1), "r"(a2), "r"(a3), "r"(b0), "r"(b1));
}

// ---------------- prep: zero accumulators + pack/pre-round weights ----------------
__global__ void k_pack(const float* __restrict__ W_gat, const float* __restrict__ W_comp_w,
                       const float* __restrict__ W_att_w, const float* __restrict__ W_go,
                       const float* __restrict__ E_atom){
    int t = blockIdx.x*256 + threadIdx.x;    // 32768 total
    {
        int k = t / (NH*GD), j = t % (NH*GD);
        int h = j / GD, f = j % GD;
        g_wcat[t] = round_tf32(W_gat[((size_t)h*CD + k)*GD + f]);
        g_wgo[t]  = round_tf32(W_go[t]);
    }
    if (t < CD*LATD){
        int k = t / LATD, l = t % LATD;
        g_wcT[t] = round_tf32(W_comp_w[(size_t)l*CD  + k]);
        g_waT[t] = round_tf32(W_att_w [(size_t)l*LATD + k]);
    }
    if (t < 100*CD) g_eat[t] = round_tf32(E_atom[t]);
    if (t < BB*LATD){ g_comp[t] = 0.f; g_prot[t] = 0.f; }
    if (t < BN){ g_src2[t] = 0.f; g_dst2[t] = 0.f; }
    { g_src1[t] = 0.f; g_dst1[t] = 0.f; }
}
__global__ void k_adjbits(const int* __restrict__ adj){
    int gid = blockIdx.x*256 + threadIdx.x;
    int v = adj[gid] > 0;
    unsigned m = __ballot_sync(0xffffffffu, v);
    if ((threadIdx.x & 31) == 0) g_adjbits[gid >> 5] = m;
}

// ---------------- tf32 mma GEMM: C[M,N] = A[M,K] @ B[K,N]  (64x64 block tile) ----------------
__global__ __launch_bounds__(256) void k_gemm(
    const float* __restrict__ A, const float* __restrict__ Bm, float* __restrict__ C,
    int N, int K, const float* __restrict__ bias, int act,
    const int* __restrict__ rowmap, const float* __restrict__ aVec, int sdMode)
{
    __shared__ uint32_t As[64*36];
    __shared__ uint32_t Bs[32*68];
    int t = threadIdx.x;
    int row0 = blockIdx.y*64, col0 = blockIdx.x*64;
    int wid = t >> 5, lane = t & 31;
    int rbase = (wid & 3)*16, cbase = (wid >> 2)*32;
    int r0 = lane >> 2, c0 = lane & 3;
    float acc[4][4];
    #pragma unroll
    for (int nb=0;nb<4;nb++){ acc[nb][0]=0.f; acc[nb][1]=0.f; acc[nb][2]=0.f; acc[nb][3]=0.f; }

    for (int k0=0; k0<K; k0+=32){
        #pragma unroll
        for (int p=0;p<2;p++){
            int r = (t >> 3) + p*32;
            int gr = row0 + r;
            int ar = rowmap ? rowmap[gr] : gr;
            float4 v = *(const float4*)(A + (size_t)ar*K + k0 + (t & 7)*4);
            *(float4*)&As[r*36 + (t & 7)*4] = v;
        }
        #pragma unroll
        for (int p=0;p<2;p++){
            int kr = (t >> 4) + p*16;
            float4 v = *(const float4*)(Bm + (size_t)(k0+kr)*N + col0 + (t & 15)*4);
            *(float4*)&Bs[kr*68 + (t & 15)*4] = v;
        }
        __syncthreads();
        #pragma unroll
        for (int kk=0; kk<32; kk+=8){
            uint32_t a0 = As[(rbase+r0)*36   + kk + c0];
            uint32_t a1 = As[(rbase+r0+8)*36 + kk + c0];
            uint32_t a2 = As[(rbase+r0)*36   + kk + c0 + 4];
            uint32_t a3 = As[(rbase+r0+8)*36 + kk + c0 + 4];
            #pragma unroll
            for (int nb=0; nb<4; nb++){
                uint32_t b0 = Bs[(kk+c0)*68   + cbase + nb*8 + r0];
                uint32_t b1 = Bs[(kk+c0+4)*68 + cbase + nb*8 + r0];
                mma_tf32(acc[nb], a0, a1, a2, a3, b0, b1);
            }
        }
        __syncthreads();
    }

    int rA = row0 + rbase + r0, rB = rA + 8;
    #pragma unroll
    for (int nb=0; nb<4; nb++){
        int col = col0 + cbase + nb*8 + 2*c0;
        float b0v = 0.f, b1v = 0.f;
        if (bias){ b0v = bias[col]; b1v = bias[col+1]; }
        float v00 = acc[nb][0]+b0v, v01 = acc[nb][1]+b1v;
        float v10 = acc[nb][2]+b0v, v11 = acc[nb][3]+b1v;
        if (act){ v00=lrelu_f(v00); v01=lrelu_f(v01); v10=lrelu_f(v10); v11=lrelu_f(v11); }
        *(float2*)(C + (size_t)rA*N + col) = make_float2(round_tf32(v00), round_tf32(v01));
        *(float2*)(C + (size_t)rB*N + col) = make_float2(round_tf32(v10), round_tf32(v11));
    }

    if (sdMode){
        float s0=0.f,d0=0.f,s1=0.f,d1=0.f;
        #pragma unroll
        for (int nb=0; nb<4; nb++){
            int col = col0 + cbase + nb*8 + 2*c0;
            const float* asv; const float* adv;
            if (sdMode == 1){
                int h = col >> 6, cc = col & 63;
                asv = aVec + (size_t)h*128 + cc;
                adv = aVec + (size_t)h*128 + 64 + cc;
            } else {
                asv = aVec + col;
                adv = aVec + 128 + col;
            }
            s0 += acc[nb][0]*asv[0] + acc[nb][1]*asv[1];
            d0 += acc[nb][0]*adv[0] + acc[nb][1]*adv[1];
            s1 += acc[nb][2]*asv[0] + acc[nb][3]*asv[1];
            d1 += acc[nb][2]*adv[0] + acc[nb][3]*adv[1];
        }
        #pragma unroll
        for (int o=1; o<4; o<<=1){
            s0 += __shfl_xor_sync(0xffffffffu, s0, o);
            d0 += __shfl_xor_sync(0xffffffffu, d0, o);
            s1 += __shfl_xor_sync(0xffffffffu, s1, o);
            d1 += __shfl_xor_sync(0xffffffffu, d1, o);
        }
        if (c0 == 0){
            s0 *= LOG2E; d0 *= LOG2E; s1 *= LOG2E; d1 *= LOG2E;
            if (sdMode == 1){
                int h = (col0 + cbase) >> 6;
                atomicAdd(&g_src1[(size_t)h*BN + rA], s0);
                atomicAdd(&g_dst1[(size_t)h*BN + rA], d0);
                atomicAdd(&g_src1[(size_t)h*BN + rB], s1);
                atomicAdd(&g_dst1[(size_t)h*BN + rB], d1);
            } else {
                atomicAdd(&g_src2[rA], s0); atomicAdd(&g_dst2[rA], d0);
                atomicAdd(&g_src2[rB], s1); atomicAdd(&g_dst2[rB], d1);
            }
        }
    }
}

// ---------------- attn1: 64 rows/block, FDIM=64 ----------------
__global__ __launch_bounds__(256) void k_attn1(
    const float* __restrict__ Wh, const float* __restrict__ src, const float* __restrict__ dst,
    float* __restrict__ out)
{
    constexpr int PAD = GD + 4;            // 68
    extern __shared__ float sm[];
    float* sbuf = sm;                      // [64][36]
    float* whs  = sbuf + 64*36;            // [32][68]
    float* dsts = whs + 32*PAD;            // [512]
    float* zz   = dsts + NA;               // [64]
    uint32_t* sbuf_u = (uint32_t*)sbuf;
    uint32_t* whs_u  = (uint32_t*)whs;

    const int b = blockIdx.y, h = blockIdx.z;
    const int row0 = blockIdx.x * 64;
    const int t = threadIdx.x;
    const int wid = t >> 5, lane = t & 31;

    const float* srcp = src + (size_t)h*BN + (size_t)b*NA;
    const float* dstp = dst + (size_t)h*BN + (size_t)b*NA;
    const float* whp  = Wh  + (size_t)b*NA*(NH*GD) + h*GD;
    float*       outp = out + ((size_t)b*NA + row0)*(NH*GD) + h*GD;

    for (int j=t; j<NA; j+=256) dsts[j] = dstp[j];

    float srcv[8], ssum[8];
    #pragma unroll
    for (int rr=0; rr<8; rr++){
        srcv[rr] = srcp[row0 + wid*8 + rr];
        ssum[rr] = 0.f;
    }
    const unsigned* bitsbase = g_adjbits + (size_t)(b*NA + row0 + wid*8)*16;
    __syncthreads();

    const int rbase = (wid & 3)*16;
    const int cbase = (wid >> 2)*32;
    const int r0 = lane >> 2, c0 = lane & 3;
    float acc[4][4];
    #pragma unroll
    for (int nb=0;nb<4;nb++){ acc[nb][0]=0.f; acc[nb][1]=0.f; acc[nb][2]=0.f; acc[nb][3]=0.f; }

    for (int jt=0; jt<NA; jt+=32){
        int it = jt >> 5;
        #pragma unroll
        for (int rr=0; rr<8; rr++){
            unsigned m = bitsbase[(size_t)rr*16 + it];
            float e = srcv[rr] + dsts[jt + lane];      // already ×log2e
            e = fmaxf(e, 0.2f*e);
            float ev = ((m >> lane) & 1u) ? exp2f(e) : 0.f;
            sbuf_u[(wid*8+rr)*36 + lane] = to_tf32(ev);
            ssum[rr] += ev;
        }
        #pragma unroll
        for (int i=t; i<32*16; i+=256){
            int row = i >> 4, c4 = i & 15;
            *(float4*)&whs_u[row*PAD + c4*4] =
                *(const float4*)&whp[(size_t)(jt+row)*(NH*GD) + c4*4];
        }
        __syncthreads();
        #pragma unroll
        for (int kk=0; kk<32; kk+=8){
            uint32_t a0 = sbuf_u[(rbase+r0)*36   + kk + c0];
            uint32_t a1 = sbuf_u[(rbase+r0+8)*36 + kk + c0];
            uint32_t a2 = sbuf_u[(rbase+r0)*36   + kk + c0 + 4];
            uint32_t a3 = sbuf_u[(rbase+r0+8)*36 + kk + c0 + 4];
            #pragma unroll
            for (int nb=0; nb<4; nb++){
                int n0 = cbase + nb*8;
                uint32_t b0 = whs_u[(kk+c0)*PAD   + n0 + r0];
                uint32_t b1 = whs_u[(kk+c0+4)*PAD + n0 + r0];
                mma_tf32(acc[nb], a0, a1, a2, a3, b0, b1);
            }
        }
        __syncthreads();
    }

    #pragma unroll
    for (int rr=0; rr<8; rr++){
        float s = ssum[rr];
        #pragma unroll
        for (int o=16;o;o>>=1) s += __shfl_xor_sync(0xffffffffu, s, o);
        if (lane==0) zz[wid*8+rr] = 1.f / s;
    }
    __syncthreads();

    float invA = zz[rbase + r0], invB = zz[rbase + r0 + 8];
    #pragma unroll
    for (int nb=0; nb<4; nb++){
        int col = cbase + nb*8 + 2*c0;
        float2 vA, vB;
        vA.x = round_tf32(elu_f(acc[nb][0]*invA)); vA.y = round_tf32(elu_f(acc[nb][1]*invA));
        vB.x = round_tf32(elu_f(acc[nb][2]*invB)); vB.y = round_tf32(elu_f(acc[nb][3]*invB));
        *(float2*)&outp[(size_t)(rbase+r0)*(NH*GD) + col]   = vA;
        *(float2*)&outp[(size_t)(rbase+r0+8)*(NH*GD) + col] = vB;
    }
}

// ---------------- attn2: 64 rows/block, FDIM=128 (halves Wh2 staging) ----------------
__global__ __launch_bounds__(256) void k_attn2(
    const float* __restrict__ Wh, const float* __restrict__ src, const float* __restrict__ dst,
    float* __restrict__ out)
{
    constexpr int FDIM = CD;
    constexpr int PAD = FDIM + 4;          // 132
    extern __shared__ float sm[];
    float* sbuf = sm;                      // [64][36]
    float* whs  = sbuf + 64*36;            // [32][132]
    float* dsts = whs + 32*PAD;            // [512]
    float* zz   = dsts + NA;               // [64]
    uint32_t* sbuf_u = (uint32_t*)sbuf;
    uint32_t* whs_u  = (uint32_t*)whs;

    const int b = blockIdx.y;
    const int row0 = blockIdx.x * 64;
    const int t = threadIdx.x;
    const int wid = t >> 5, lane = t & 31;

    const float* srcp = src + (size_t)b*NA;
    const float* dstp = dst + (size_t)b*NA;
    const float* whp  = Wh  + (size_t)b*NA*FDIM;
    float*       outp = out + ((size_t)b*NA + row0)*FDIM;

    for (int j=t; j<NA; j+=256) dsts[j] = dstp[j];

    float srcv[8], ssum[8];
    #pragma unroll
    for (int rr=0; rr<8; rr++){
        srcv[rr] = srcp[row0 + wid*8 + rr];
        ssum[rr] = 0.f;
    }
    const unsigned* bitsbase = g_adjbits + (size_t)(b*NA + row0 + wid*8)*16;
    __syncthreads();

    const int rbase = (wid & 3)*16;        // 4 row tiles
    const int cbase = (wid >> 2)*64;       // 2 col halves of 64
    const int r0 = lane >> 2, c0 = lane & 3;
    float acc[8][4];
    #pragma unroll
    for (int nb=0;nb<8;nb++){ acc[nb][0]=0.f; acc[nb][1]=0.f; acc[nb][2]=0.f; acc[nb][3]=0.f; }

    for (int jt=0; jt<NA; jt+=32){
        int it = jt >> 5;
        #pragma unroll
        for (int rr=0; rr<8; rr++){
            unsigned m = bitsbase[(size_t)rr*16 + it];
            float e = srcv[rr] + dsts[jt + lane];
            e = fmaxf(e, 0.2f*e);
            float ev = ((m >> lane) & 1u) ? exp2f(e) : 0.f;
            sbuf_u[(wid*8+rr)*36 + lane] = to_tf32(ev);
            ssum[rr] += ev;
        }
        #pragma unroll
        for (int i=t; i<32*32; i+=256){
            int row = i >> 5, c4 = i & 31;
            *(float4*)&whs_u[row*PAD + c4*4] =
                *(const float4*)&whp[(size_t)(jt+row)*FDIM + c4*4];
        }
        __syncthreads();
        #pragma unroll
        for (int kk=0; kk<32; kk+=8){
            uint32_t a0 = sbuf_u[(rbase+r0)*36   + kk + c0];
            uint32_t a1 = sbuf_u[(rbase+r0+8)*36 + kk + c0];
            uint32_t a2 = sbuf_u[(rbase+r0)*36   + kk + c0 + 4];
            uint32_t a3 = sbuf_u[(rbase+r0+8)*36 + kk + c0 + 4];
            #pragma unroll
            for (int nb=0; nb<8; nb++){
                int n0 = cbase + nb*8;
                uint32_t b0 = whs_u[(kk+c0)*PAD   + n0 + r0];
                uint32_t b1 = whs_u[(kk+c0+4)*PAD + n0 + r0];
                mma_tf32(acc[nb], a0, a1, a2, a3, b0, b1);
            }
        }
        __syncthreads();
    }

    #pragma unroll
    for (int rr=0; rr<8; rr++){
        float s = ssum[rr];
        #pragma unroll
        for (int o=16;o;o>>=1) s += __shfl_xor_sync(0xffffffffu, s, o);
        if (lane==0) zz[wid*8+rr] = 1.f / s;
    }
    __syncthreads();

    float invA = zz[rbase + r0], invB = zz[rbase + r0 + 8];
    #pragma unroll
    for (int nb=0; nb<8; nb++){
        int col = cbase + nb*8 + 2*c0;
        float2 vA, vB;
        vA.x = round_tf32(elu_f(acc[nb][0]*invA)); vA.y = round_tf32(elu_f(acc[nb][1]*invA));
        vB.x = round_tf32(elu_f(acc[nb][2]*invB)); vB.y = round_tf32(elu_f(acc[nb][3]*invB));
        *(float2*)&outp[(size_t)(rbase+r0)*FDIM + col]   = vA;
        *(float2*)&outp[(size_t)(rbase+r0+8)*FDIM + col] = vB;
    }
}

// ---------------- 11x11 SAME conv + relu: transposed tile + transposed float4 weights ----------------
__global__ __launch_bounds__(256, 4) void k_conv(
    const float* __restrict__ in, float* __restrict__ out,
    const float* __restrict__ wAll, const float* __restrict__ bAll, int layer,
    const int* __restrict__ aminoIdx, const float* __restrict__ E, int roundOut)
{
    __shared__ float tileT[42*84];
    __shared__ float wsT[11*12];       // [dx][dy], dy 11 padded to 12 (zero pad)
    int bx = blockIdx.x, by = blockIdx.y, bz = blockIdx.z;
    int tx = threadIdx.x, ty = threadIdx.y;   // 32 x 8
    int t = ty*32 + tx;
    int wid = t >> 5, lane = t & 31;
    if (t < 132){
        int dx = t / 12, dy = t % 12;
        wsT[t] = (dy < 11) ? wAll[layer*121 + dy*11 + dx] : 0.f;
    }
    int x0 = bx*32 - 5, y0 = by*64 - 5;
    const float* inb = in + (size_t)bz*LA*CD;
    const int*   amb = aminoIdx ? aminoIdx + (size_t)bz*LA : nullptr;

    for (int g = wid; g < 19; g += 8){
        int row0 = g*4;
        float v[4];
        #pragma unroll
        for (int j=0;j<4;j++){
            int ly = row0 + j;
            int gy = y0 + ly, gx = x0 + lane;
            float val = 0.f;
            if (ly < 74 && gy >= 0 && gy < LA && gx >= 0 && gx < CD)
                val = amb ? E[(size_t)amb[gy]*CD + gx] : inb[(size_t)gy*CD + gx];
            v[j] = val;
        }
        *(float4*)&tileT[lane*84 + row0] = make_float4(v[0],v[1],v[2],v[3]);
        if (lane < 10){
            #pragma unroll
            for (int j=0;j<4;j++){
                int ly = row0 + j;
                int gy = y0 + ly, gx = x0 + 32 + lane;
                float val = 0.f;
                if (ly < 74 && gy >= 0 && gy < LA && gx >= 0 && gx < CD)
                    val = amb ? E[(size_t)amb[gy]*CD + gx] : inb[(size_t)gy*CD + gx];
                v[j] = val;
            }
            *(float4*)&tileT[(32+lane)*84 + row0] = make_float4(v[0],v[1],v[2],v[3]);
        }
    }
    __syncthreads();

    float bb = bAll[layer];
    float acc[8];
    #pragma unroll
    for (int q=0;q<8;q++) acc[q] = bb;
    #pragma unroll
    for (int dx=0; dx<11; dx++){
        float4 rv4[5];
        #pragma unroll
        for (int g=0;g<5;g++)
            rv4[g] = *(const float4*)&tileT[(tx+dx)*84 + ty*8 + g*4];
        const float* rv = (const float*)rv4;
        float4 w0 = *(const float4*)&wsT[dx*12];
        float4 w1 = *(const float4*)&wsT[dx*12 + 4];
        float4 w2 = *(const float4*)&wsT[dx*12 + 8];
        const float wv[12] = {w0.x,w0.y,w0.z,w0.w, w1.x,w1.y,w1.z,w1.w, w2.x,w2.y,w2.z,w2.w};
        #pragma unroll
        for (int dy=0; dy<11; dy++){
            #pragma unroll
            for (int q=0;q<8;q++) acc[q] += rv[q+dy]*wv[dy];
        }
    }
    float* ob = out + (size_t)bz*LA*CD + (size_t)(by*64 + ty*8)*CD + bx*32 + tx;
    #pragma unroll
    for (int q=0;q<8;q++){
        float v = fmaxf(acc[q], 0.f);
        ob[(size_t)q*CD] = roundOut ? round_tf32(v) : v;
    }
}

// ---------------- attention pool (tf32 mma) ----------------
__global__ __launch_bounds__(256) void k_pool(
    const float* __restrict__ vec, const float* __restrict__ mask,
    const float* __restrict__ ba, float* __restrict__ outAcc, int R)
{
    __shared__ uint32_t As[32*36];
    __shared__ uint32_t Bs[32*132];
    __shared__ float mks[32];
    int b = blockIdx.y;
    int r0tile = blockIdx.x*32;
    int t = threadIdx.x;
    int wid = t >> 5, lane = t & 31;
    int rbase = (wid & 1)*16, cbase = (wid >> 1)*32;
    int r0 = lane >> 2, c0 = lane & 3;

    if (t < 32) mks[t] = mask[(size_t)b*R + r0tile + t];

    float acc[4][4];
    #pragma unroll
    for (int nb=0;nb<4;nb++){ acc[nb][0]=0.f; acc[nb][1]=0.f; acc[nb][2]=0.f; acc[nb][3]=0.f; }

    for (int k0=0; k0<LATD; k0+=32){
        {
            int r = t >> 3;
            float4 v = *(const float4*)(vec + ((size_t)b*R + r0tile + r)*LATD + k0 + (t & 7)*4);
            *(float4*)&As[r*36 + (t & 7)*4] = v;
        }
        #pragma unroll
        for (int p=0;p<4;p++){
            int kr = (t >> 5) + p*8;
            float4 v = *(const float4*)(g_waT + (size_t)(k0+kr)*LATD + (t & 31)*4);
            *(float4*)&Bs[kr*132 + (t & 31)*4] = v;
        }
        __syncthreads();
        #pragma unroll
        for (int kk=0; kk<32; kk+=8){
            uint32_t a0 = As[(rbase+r0)*36   + kk + c0];
            uint32_t a1 = As[(rbase+r0+8)*36 + kk + c0];
            uint32_t a2 = As[(rbase+r0)*36   + kk + c0 + 4];
            uint32_t a3 = As[(rbase+r0+8)*36 + kk + c0 + 4];
            #pragma unroll
            for (int nb=0; nb<4; nb++){
                uint32_t b0 = Bs[(kk+c0)*132   + cbase + nb*8 + r0];
                uint32_t b1 = Bs[(kk+c0+4)*132 + cbase + nb*8 + r0];
                mma_tf32(acc[nb], a0, a1, a2, a3, b0, b1);
            }
        }
        __syncthreads();
    }

    float m0 = mks[rbase + r0], m1 = mks[rbase + r0 + 8];
    #pragma unroll
    for (int nb=0; nb<4; nb++){
        int col = cbase + nb*8 + 2*c0;
        float bb0 = ba[col], bb1 = ba[col+1];
        float cs0 = lrelu_f(acc[nb][0] + bb0)*m0 + lrelu_f(acc[nb][2] + bb0)*m1;
        float cs1 = lrelu_f(acc[nb][1] + bb1)*m0 + lrelu_f(acc[nb][3] + bb1)*m1;
        #pragma unroll
        for (int o=4; o<32; o<<=1){
            cs0 += __shfl_xor_sync(0xffffffffu, cs0, o);
            cs1 += __shfl_xor_sync(0xffffffffu, cs1, o);
        }
        if (r0 == 0){
            atomicAdd(&outAcc[(size_t)b*LATD + col],     cs0);
            atomicAdd(&outAcc[(size_t)b*LATD + col + 1], cs1);
        }
    }
}

// ---------------- final head ----------------
__global__ void k_final(const float* __restrict__ amask, const float* __restrict__ pmask,
                        const float* __restrict__ pw, const float* __restrict__ pb,
                        float* __restrict__ outp)
{
    int b = blockIdx.x, t = threadIdx.x;
    __shared__ float red[256];
    __shared__ float sums[2];
    float sa = 0.f;
    for (int i=t; i<NA; i+=256) sa += amask[(size_t)b*NA + i];
    red[t] = sa; __syncthreads();
    for (int o=128;o;o>>=1){ if (t<o) red[t] += red[t+o]; __syncthreads(); }
    if (t==0) sums[0] = red[0];
    __syncthreads();
    float sp = 0.f;
    for (int i=t; i<LA; i+=256) sp += pmask[(size_t)b*LA + i];
    red[t] = sp; __syncthreads();
    for (int o=128;o;o>>=1){ if (t<o) red[t] += red[t+o]; __syncthreads(); }
    if (t==0) sums[1] = red[0];
    __syncthreads();
    float v = (t < LATD) ? g_comp[(size_t)b*LATD + t] / sums[0]
                         : g_prot[(size_t)b*LATD + (t-LATD)] / sums[1];
    v = lrelu_f(lrelu_f(v));
    red[t] = v * pw[t]; __syncthreads();
    for (int o=128;o;o>>=1){ if (t<o) red[t] += red[t+o]; __syncthreads(); }
    if (t==0) outp[b] = red[0] + pb[0];
}

// ---------------- launch (2-stream fork/join) ----------------
extern "C" void kernel_launch(void* const* d_in, const int* in_sizes, int n_in,
                              void* d_out, int out_size)
{
    const int*   atoms      = (const int*)  d_in[0];
    const float* atoms_mask = (const float*)d_in[1];
    const int*   adjacency  = (const int*)  d_in[2];
    const int*   amino      = (const int*)  d_in[3];
    const float* amino_mask = (const float*)d_in[4];
    const float* E_atom     = (const float*)d_in[5];
    const float* E_amino    = (const float*)d_in[6];
    const float* W_gat      = (const float*)d_in[7];
    const float* a_gat      = (const float*)d_in[8];
    const float* W_go       = (const float*)d_in[9];
    const float* a_go       = (const float*)d_in[10];
    const float* W_comp_w   = (const float*)d_in[11];
    const float* W_comp_b   = (const float*)d_in[12];
    const float* conv_w     = (const float*)d_in[13];
    const float* conv_b     = (const float*)d_in[14];
    const float* W_att_w    = (const float*)d_in[15];
    const float* W_att_b    = (const float*)d_in[16];
    const float* pred_w     = (const float*)d_in[17];
    const float* pred_b     = (const float*)d_in[18];
    float* outp = (float*)d_out;

    float *p_wcat, *p_wgo, *p_eat, *p_wh, *p_src1, *p_dst1, *p_multi, *p_wh2, *p_src2, *p_dst2;
    float *p_x, *p_wcT, *p_avec, *p_pv0, *p_pv1, *p_comp, *p_prot;
    cudaGetSymbolAddress((void**)&p_wcat,  g_wcat);
    cudaGetSymbolAddress((void**)&p_wgo,   g_wgo);
    cudaGetSymbolAddress((void**)&p_eat,   g_eat);
    cudaGetSymbolAddress((void**)&p_wh,    g_wh);
    cudaGetSymbolAddress((void**)&p_src1,  g_src1);
    cudaGetSymbolAddress((void**)&p_dst1,  g_dst1);
    cudaGetSymbolAddress((void**)&p_multi, g_multi);
    cudaGetSymbolAddress((void**)&p_wh2,   g_wh2);
    cudaGetSymbolAddress((void**)&p_src2,  g_src2);
    cudaGetSymbolAddress((void**)&p_dst2,  g_dst2);
    cudaGetSymbolAddress((void**)&p_x,     g_x);
    cudaGetSymbolAddress((void**)&p_wcT,   g_wcT);
    cudaGetSymbolAddress((void**)&p_avec,  g_avec);
    cudaGetSymbolAddress((void**)&p_pv0,   g_pv0);
    cudaGetSymbolAddress((void**)&p_pv1,   g_pv1);
    cudaGetSymbolAddress((void**)&p_comp,  g_comp);
    cudaGetSymbolAddress((void**)&p_prot,  g_prot);

    const int SM1 = (64*36 + 32*(GD+4)  + NA + 64) * 4;   // 23808 B
    const int SM2 = (64*36 + 32*(CD+4)  + NA + 64) * 4;   // 28416 B

    static cudaStream_t s2 = nullptr;
    static cudaEvent_t evFork = nullptr, evAdj = nullptr, evJoin = nullptr;
    if (!s2){
        cudaStreamCreateWithFlags(&s2, cudaStreamNonBlocking);
        cudaEventCreateWithFlags(&evFork, cudaEventDisableTiming);
        cudaEventCreateWithFlags(&evAdj,  cudaEventDisableTiming);
        cudaEventCreateWithFlags(&evJoin, cudaEventDisableTiming);
    }

    // ---- fork FIRST: side stream is independent of k_pack ----
    cudaEventRecord(evFork, 0);
    cudaStreamWaitEvent(s2, evFork, 0);

    // ---- side stream: adjacency bitmask, then amino path ----
    k_adjbits<<<BN*NA/256, 256, 0, s2>>>(adjacency);
    cudaEventRecord(evAdj, s2);
    k_conv<<<dim3(4,16,BB), dim3(32,8), 0, s2>>>(p_pv1, p_pv0, conv_w, conv_b, 0, amino, E_amino, 0);
    k_conv<<<dim3(4,16,BB), dim3(32,8), 0, s2>>>(p_pv0, p_pv1, conv_w, conv_b, 1, nullptr, nullptr, 0);
    k_conv<<<dim3(4,16,BB), dim3(32,8), 0, s2>>>(p_pv1, p_pv0, conv_w, conv_b, 2, nullptr, nullptr, 1);
    k_pool<<<dim3(LA/32, BB), 256, 0, s2>>>(p_pv0, amino_mask, W_att_b, p_prot, LA);
    cudaEventRecord(evJoin, s2);

    // ---- atom path on main stream ----
    k_pack<<<128, 256>>>(W_gat, W_comp_w, W_att_w, W_go, E_atom);
    k_gemm<<<dim3(4,128), 256>>>(p_eat, p_wcat, p_wh, NH*GD, CD, nullptr, 0, atoms, a_gat, 1);
    cudaStreamWaitEvent(0, evAdj, 0);
    k_attn1<<<dim3(NA/64, BB, NH), 256, SM1>>>(p_wh, p_src1, p_dst1, p_multi);
    k_gemm<<<dim3(2,128), 256>>>(p_multi, p_wgo, p_wh2, CD, NH*GD, nullptr, 0, nullptr, a_go, 2);
    k_attn2<<<dim3(NA/64, BB), 256, SM2>>>(p_wh2, p_src2, p_dst2, p_x);
    k_gemm<<<dim3(2,128), 256>>>(p_x, p_wcT, p_avec, LATD, CD, W_comp_b, 1, nullptr, nullptr, 0);
    k_pool<<<dim3(NA/32, BB), 256>>>(p_avec, atoms_mask, W_att_b, p_comp, NA);

    // ---- join + head ----
    cudaStreamWaitEvent(0, evJoin, 0);
    k_final<<<BB, 256>>>(atoms_mask, amino_mask, pred_w, pred_b, outp);
}

// round 16
// speedup vs baseline: 1.0437x; 1.0437x over previous
#include <cuda_runtime.h>
#include <cstdint>
#include <math.h>

// ---------------- problem constants ----------------
#define BB   16
#define NA   512
#define LA   1024
#define CD   128
#define GD   64
#define NH   4
#define LATD 128
#define BN   (BB*NA)
#define LOG2E 1.4426950408889634f

// ---------------- device scratch ----------------
__device__ float    g_wcat [CD*NH*GD];     // pre-rounded tf32
__device__ float    g_wgo  [NH*GD*CD];     // pre-rounded W_go copy
__device__ float    g_eat  [100*CD];       // pre-rounded E_atom
__device__ float    g_wh   [BN*NH*GD];
__device__ float    g_src1 [NH*BN];        // pre-scaled by log2e
__device__ float    g_dst1 [NH*BN];
__device__ float    g_multi[BN*NH*GD];
__device__ float    g_wh2  [BN*CD];
__device__ float    g_src2 [BN];
__device__ float    g_dst2 [BN];
__device__ float    g_x    [BN*CD];
__device__ float    g_wcT  [CD*LATD];
__device__ float    g_waT  [LATD*LATD];
__device__ float    g_avec [BN*LATD];
__device__ float    g_pv0  [BB*LA*CD];
__device__ float    g_pv1  [BB*LA*CD];
__device__ float    g_comp [BB*LATD];
__device__ float    g_prot [BB*LATD];
__device__ unsigned g_adjbits[BN*16];

__device__ __forceinline__ float lrelu_f(float x){ return x > 0.f ? x : 0.2f*x; }
__device__ __forceinline__ float elu_f(float x){ return x > 0.f ? x : (__expf(x) - 1.f); }

__device__ __forceinline__ uint32_t to_tf32(float f){
    uint32_t u; asm("cvt.rna.tf32.f32 %0, %1;" : "=r"(u) : "f"(f)); return u;
}
__device__ __forceinline__ float round_tf32(float f){ return __uint_as_float(to_tf32(f)); }
__device__ __forceinline__ void mma_tf32(float* d,
    uint32_t a0, uint32_t a1, uint32_t a2, uint32_t a3, uint32_t b0, uint32_t b1){
    asm volatile("mma.sync.aligned.m16n8k8.row.col.f32.tf32.tf32.f32 "
        "{%0,%1,%2,%3}, {%4,%5,%6,%7}, {%8,%9}, {%0,%1,%2,%3};"
        : "+f"(d[0]), "+f"(d[1]), "+f"(d[2]), "+f"(d[3])
        : "r"(a0), "r"(a1), "r"(a2), "r"(a3), "r"(b0), "r"(b1));
}

// ---------------- prep: zero accumulators + pack/pre-round weights ----------------
__global__ void k_pack(const float* __restrict__ W_gat, const float* __restrict__ W_comp_w,
                       const float* __restrict__ W_att_w, const float* __restrict__ W_go,
                       const float* __restrict__ E_atom){
    int t = blockIdx.x*256 + threadIdx.x;    // 32768 total
    {
        int k = t / (NH*GD), j = t % (NH*GD);
        int h = j / GD, f = j % GD;
        g_wcat[t] = round_tf32(W_gat[((size_t)h*CD + k)*GD + f]);
        g_wgo[t]  = round_tf32(W_go[t]);
    }
    if (t < CD*LATD){
        int k = t / LATD, l = t % LATD;
        g_wcT[t] = round_tf32(W_comp_w[(size_t)l*CD  + k]);
        g_waT[t] = round_tf32(W_att_w [(size_t)l*LATD + k]);
    }
    if (t < 100*CD) g_eat[t] = round_tf32(E_atom[t]);
    if (t < BB*LATD){ g_comp[t] = 0.f; g_prot[t] = 0.f; }
    if (t < BN){ g_src2[t] = 0.f; g_dst2[t] = 0.f; }
    { g_src1[t] = 0.f; g_dst1[t] = 0.f; }
}
__global__ void k_adjbits(const int* __restrict__ adj){
    int gid = blockIdx.x*256 + threadIdx.x;
    int v = adj[gid] > 0;
    unsigned m = __ballot_sync(0xffffffffu, v);
    if ((threadIdx.x & 31) == 0) g_adjbits[gid >> 5] = m;
}

// ---------------- tf32 mma GEMM: C[M,N] = A[M,K] @ B[K,N]  (64x64 block tile) ----------------
__global__ __launch_bounds__(256) void k_gemm(
    const float* __restrict__ A, const float* __restrict__ Bm, float* __restrict__ C,
    int N, int K, const float* __restrict__ bias, int act,
    const int* __restrict__ rowmap, const float* __restrict__ aVec, int sdMode)
{
    __shared__ uint32_t As[64*36];
    __shared__ uint32_t Bs[32*68];
    int t = threadIdx.x;
    int row0 = blockIdx.y*64, col0 = blockIdx.x*64;
    int wid = t >> 5, lane = t & 31;
    int rbase = (wid & 3)*16, cbase = (wid >> 2)*32;
    int r0 = lane >> 2, c0 = lane & 3;
    float acc[4][4];
    #pragma unroll
    for (int nb=0;nb<4;nb++){ acc[nb][0]=0.f; acc[nb][1]=0.f; acc[nb][2]=0.f; acc[nb][3]=0.f; }

    for (int k0=0; k0<K; k0+=32){
        #pragma unroll
        for (int p=0;p<2;p++){
            int r = (t >> 3) + p*32;
            int gr = row0 + r;
            int ar = rowmap ? rowmap[gr] : gr;
            float4 v = *(const float4*)(A + (size_t)ar*K + k0 + (t & 7)*4);
            *(float4*)&As[r*36 + (t & 7)*4] = v;
        }
        #pragma unroll
        for (int p=0;p<2;p++){
            int kr = (t >> 4) + p*16;
            float4 v = *(const float4*)(Bm + (size_t)(k0+kr)*N + col0 + (t & 15)*4);
            *(float4*)&Bs[kr*68 + (t & 15)*4] = v;
        }
        __syncthreads();
        #pragma unroll
        for (int kk=0; kk<32; kk+=8){
            uint32_t a0 = As[(rbase+r0)*36   + kk + c0];
            uint32_t a1 = As[(rbase+r0+8)*36 + kk + c0];
            uint32_t a2 = As[(rbase+r0)*36   + kk + c0 + 4];
            uint32_t a3 = As[(rbase+r0+8)*36 + kk + c0 + 4];
            #pragma unroll
            for (int nb=0; nb<4; nb++){
                uint32_t b0 = Bs[(kk+c0)*68   + cbase + nb*8 + r0];
                uint32_t b1 = Bs[(kk+c0+4)*68 + cbase + nb*8 + r0];
                mma_tf32(acc[nb], a0, a1, a2, a3, b0, b1);
            }
        }
        __syncthreads();
    }

    int rA = row0 + rbase + r0, rB = rA + 8;
    #pragma unroll
    for (int nb=0; nb<4; nb++){
        int col = col0 + cbase + nb*8 + 2*c0;
        float b0v = 0.f, b1v = 0.f;
        if (bias){ b0v = bias[col]; b1v = bias[col+1]; }
        float v00 = acc[nb][0]+b0v, v01 = acc[nb][1]+b1v;
        float v10 = acc[nb][2]+b0v, v11 = acc[nb][3]+b1v;
        if (act){ v00=lrelu_f(v00); v01=lrelu_f(v01); v10=lrelu_f(v10); v11=lrelu_f(v11); }
        *(float2*)(C + (size_t)rA*N + col) = make_float2(round_tf32(v00), round_tf32(v01));
        *(float2*)(C + (size_t)rB*N + col) = make_float2(round_tf32(v10), round_tf32(v11));
    }

    if (sdMode){
        float s0=0.f,d0=0.f,s1=0.f,d1=0.f;
        #pragma unroll
        for (int nb=0; nb<4; nb++){
            int col = col0 + cbase + nb*8 + 2*c0;
            const float* asv; const float* adv;
            if (sdMode == 1){
                int h = col >> 6, cc = col & 63;
                asv = aVec + (size_t)h*128 + cc;
                adv = aVec + (size_t)h*128 + 64 + cc;
            } else {
                asv = aVec + col;
                adv = aVec + 128 + col;
            }
            s0 += acc[nb][0]*asv[0] + acc[nb][1]*asv[1];
            d0 += acc[nb][0]*adv[0] + acc[nb][1]*adv[1];
            s1 += acc[nb][2]*asv[0] + acc[nb][3]*asv[1];
            d1 += acc[nb][2]*adv[0] + acc[nb][3]*adv[1];
        }
        #pragma unroll
        for (int o=1; o<4; o<<=1){
            s0 += __shfl_xor_sync(0xffffffffu, s0, o);
            d0 += __shfl_xor_sync(0xffffffffu, d0, o);
            s1 += __shfl_xor_sync(0xffffffffu, s1, o);
            d1 += __shfl_xor_sync(0xffffffffu, d1, o);
        }
        if (c0 == 0){
            s0 *= LOG2E; d0 *= LOG2E; s1 *= LOG2E; d1 *= LOG2E;
            if (sdMode == 1){
                int h = (col0 + cbase) >> 6;
                atomicAdd(&g_src1[(size_t)h*BN + rA], s0);
                atomicAdd(&g_dst1[(size_t)h*BN + rA], d0);
                atomicAdd(&g_src1[(size_t)h*BN + rB], s1);
                atomicAdd(&g_dst1[(size_t)h*BN + rB], d1);
            } else {
                atomicAdd(&g_src2[rA], s0); atomicAdd(&g_dst2[rA], d0);
                atomicAdd(&g_src2[rB], s1); atomicAdd(&g_dst2[rB], d1);
            }
        }
    }
}

// ---------------- attn1: 64 rows/block, FDIM=64 ----------------
__global__ __launch_bounds__(256) void k_attn1(
    const float* __restrict__ Wh, const float* __restrict__ src, const float* __restrict__ dst,
    float* __restrict__ out)
{
    constexpr int PAD = GD + 4;            // 68
    extern __shared__ float sm[];
    float* sbuf = sm;                      // [64][36]
    float* whs  = sbuf + 64*36;            // [32][68]
    float* dsts = whs + 32*PAD;            // [512]
    float* zz   = dsts + NA;               // [64]
    uint32_t* sbuf_u = (uint32_t*)sbuf;
    uint32_t* whs_u  = (uint32_t*)whs;

    const int b = blockIdx.y, h = blockIdx.z;
    const int row0 = blockIdx.x * 64;
    const int t = threadIdx.x;
    const int wid = t >> 5, lane = t & 31;

    const float* srcp = src + (size_t)h*BN + (size_t)b*NA;
    const float* dstp = dst + (size_t)h*BN + (size_t)b*NA;
    const float* whp  = Wh  + (size_t)b*NA*(NH*GD) + h*GD;
    float*       outp = out + ((size_t)b*NA + row0)*(NH*GD) + h*GD;

    for (int j=t; j<NA; j+=256) dsts[j] = dstp[j];

    float srcv[8], ssum[8];
    #pragma unroll
    for (int rr=0; rr<8; rr++){
        srcv[rr] = srcp[row0 + wid*8 + rr];
        ssum[rr] = 0.f;
    }
    const unsigned* bitsbase = g_adjbits + (size_t)(b*NA + row0 + wid*8)*16;
    __syncthreads();

    const int rbase = (wid & 3)*16;
    const int cbase = (wid >> 2)*32;
    const int r0 = lane >> 2, c0 = lane & 3;
    float acc[4][4];
    #pragma unroll
    for (int nb=0;nb<4;nb++){ acc[nb][0]=0.f; acc[nb][1]=0.f; acc[nb][2]=0.f; acc[nb][3]=0.f; }

    for (int jt=0; jt<NA; jt+=32){
        int it = jt >> 5;
        #pragma unroll
        for (int rr=0; rr<8; rr++){
            unsigned m = bitsbase[(size_t)rr*16 + it];
            float e = srcv[rr] + dsts[jt + lane];      // already ×log2e
            e = fmaxf(e, 0.2f*e);
            float ev = ((m >> lane) & 1u) ? exp2f(e) : 0.f;
            sbuf_u[(wid*8+rr)*36 + lane] = to_tf32(ev);
            ssum[rr] += ev;
        }
        #pragma unroll
        for (int i=t; i<32*16; i+=256){
            int row = i >> 4, c4 = i & 15;
            *(float4*)&whs_u[row*PAD + c4*4] =
                *(const float4*)&whp[(size_t)(jt+row)*(NH*GD) + c4*4];
        }
        __syncthreads();
        #pragma unroll
        for (int kk=0; kk<32; kk+=8){
            uint32_t a0 = sbuf_u[(rbase+r0)*36   + kk + c0];
            uint32_t a1 = sbuf_u[(rbase+r0+8)*36 + kk + c0];
            uint32_t a2 = sbuf_u[(rbase+r0)*36   + kk + c0 + 4];
            uint32_t a3 = sbuf_u[(rbase+r0+8)*36 + kk + c0 + 4];
            #pragma unroll
            for (int nb=0; nb<4; nb++){
                int n0 = cbase + nb*8;
                uint32_t b0 = whs_u[(kk+c0)*PAD   + n0 + r0];
                uint32_t b1 = whs_u[(kk+c0+4)*PAD + n0 + r0];
                mma_tf32(acc[nb], a0, a1, a2, a3, b0, b1);
            }
        }
        __syncthreads();
    }

    #pragma unroll
    for (int rr=0; rr<8; rr++){
        float s = ssum[rr];
        #pragma unroll
        for (int o=16;o;o>>=1) s += __shfl_xor_sync(0xffffffffu, s, o);
        if (lane==0) zz[wid*8+rr] = 1.f / s;
    }
    __syncthreads();

    float invA = zz[rbase + r0], invB = zz[rbase + r0 + 8];
    #pragma unroll
    for (int nb=0; nb<4; nb++){
        int col = cbase + nb*8 + 2*c0;
        float2 vA, vB;
        vA.x = round_tf32(elu_f(acc[nb][0]*invA)); vA.y = round_tf32(elu_f(acc[nb][1]*invA));
        vB.x = round_tf32(elu_f(acc[nb][2]*invB)); vB.y = round_tf32(elu_f(acc[nb][3]*invB));
        *(float2*)&outp[(size_t)(rbase+r0)*(NH*GD) + col]   = vA;
        *(float2*)&outp[(size_t)(rbase+r0+8)*(NH*GD) + col] = vB;
    }
}

// ---------------- attn2: 32 rows/block, FDIM=128 (R14 shape: 256-block grid) ----------------
__global__ __launch_bounds__(256) void k_attn2(
    const float* __restrict__ Wh, const float* __restrict__ src, const float* __restrict__ dst,
    float* __restrict__ out)
{
    constexpr int FDIM = CD;
    constexpr int PAD = FDIM + 4;
    constexpr int FG  = FDIM / 4;
    constexpr int NB  = FDIM / 32;
    extern __shared__ float sm[];
    float* sbuf = sm;                      // [32][36]
    float* whs  = sbuf + 32*36;            // [32][PAD]
    float* dsts = whs + 32*PAD;            // [512]
    float* zz   = dsts + NA;               // [32]
    uint32_t* sbuf_u = (uint32_t*)sbuf;
    uint32_t* whs_u  = (uint32_t*)whs;

    const int b = blockIdx.y;
    const int row0 = blockIdx.x * 32;
    const int t = threadIdx.x;
    const int wid = t >> 5, lane = t & 31;

    const float* srcp = src + (size_t)b*NA;
    const float* dstp = dst + (size_t)b*NA;
    const float* whp  = Wh  + (size_t)b*NA*FDIM;
    float*       outp = out + ((size_t)b*NA + row0)*FDIM;

    for (int j=t; j<NA; j+=256) dsts[j] = dstp[j];

    float srcv[4], ssum[4];
    const unsigned* brow[4];
    #pragma unroll
    for (int rr=0; rr<4; rr++){
        int r = wid*4 + rr;
        srcv[rr] = srcp[row0 + r];
        ssum[rr] = 0.f;
        brow[rr] = g_adjbits + (size_t)(b*NA + row0 + r)*16;
    }
    __syncthreads();

    const int rbase = (wid & 1)*16;
    const int cgrp  = wid >> 1;
    const int r0 = lane >> 2, c0 = lane & 3;
    float acc[NB][4];
    #pragma unroll
    for (int nb=0;nb<NB;nb++){ acc[nb][0]=0.f; acc[nb][1]=0.f; acc[nb][2]=0.f; acc[nb][3]=0.f; }

    for (int jt=0; jt<NA; jt+=32){
        int it = jt >> 5;
        #pragma unroll
        for (int rr=0; rr<4; rr++){
            unsigned m = brow[rr][it];
            float e = srcv[rr] + dsts[jt + lane];
            e = fmaxf(e, 0.2f*e);
            float ev = ((m >> lane) & 1u) ? exp2f(e) : 0.f;
            sbuf_u[(wid*4+rr)*36 + lane] = to_tf32(ev);
            ssum[rr] += ev;
        }
        #pragma unroll
        for (int i=t; i<32*FG; i+=256){
            int row = i / FG, c4 = i % FG;
            *(float4*)&whs_u[row*PAD + c4*4] =
                *(const float4*)&whp[(size_t)(jt+row)*FDIM + c4*4];
        }
        __syncthreads();
        #pragma unroll
        for (int kk=0; kk<32; kk+=8){
            uint32_t a0 = sbuf_u[(rbase+r0)*36   + kk + c0];
            uint32_t a1 = sbuf_u[(rbase+r0+8)*36 + kk + c0];
            uint32_t a2 = sbuf_u[(rbase+r0)*36   + kk + c0 + 4];
            uint32_t a3 = sbuf_u[(rbase+r0+8)*36 + kk + c0 + 4];
            #pragma unroll
            for (int nb=0; nb<NB; nb++){
                int n0 = cgrp*(8*NB) + nb*8;
                uint32_t b0 = whs_u[(kk+c0)*PAD   + n0 + r0];
                uint32_t b1 = whs_u[(kk+c0+4)*PAD + n0 + r0];
                mma_tf32(acc[nb], a0, a1, a2, a3, b0, b1);
            }
        }
        __syncthreads();
    }

    #pragma unroll
    for (int rr=0; rr<4; rr++){
        float s = ssum[rr];
        #pragma unroll
        for (int o=16;o;o>>=1) s += __shfl_xor_sync(0xffffffffu, s, o);
        if (lane==0) zz[wid*4+rr] = 1.f / s;
    }
    __syncthreads();

    float invA = zz[rbase + r0], invB = zz[rbase + r0 + 8];
    #pragma unroll
    for (int nb=0; nb<NB; nb++){
        int col = cgrp*(8*NB) + nb*8 + 2*c0;
        float2 vA, vB;
        vA.x = round_tf32(elu_f(acc[nb][0]*invA)); vA.y = round_tf32(elu_f(acc[nb][1]*invA));
        vB.x = round_tf32(elu_f(acc[nb][2]*invB)); vB.y = round_tf32(elu_f(acc[nb][3]*invB));
        *(float2*)&outp[(size_t)(rbase+r0)*FDIM + col]   = vA;
        *(float2*)&outp[(size_t)(rbase+r0+8)*FDIM + col] = vB;
    }
}

// ---------------- 11x11 SAME conv + relu: transposed tile + transposed float4 weights ----------------
__global__ __launch_bounds__(256, 4) void k_conv(
    const float* __restrict__ in, float* __restrict__ out,
    const float* __restrict__ wAll, const float* __restrict__ bAll, int layer,
    const int* __restrict__ aminoIdx, const float* __restrict__ E, int roundOut)
{
    __shared__ float tileT[42*84];
    __shared__ float wsT[11*12];       // [dx][dy], dy 11 padded to 12
    int bx = blockIdx.x, by = blockIdx.y, bz = blockIdx.z;
    int tx = threadIdx.x, ty = threadIdx.y;   // 32 x 8
    int t = ty*32 + tx;
    int wid = t >> 5, lane = t & 31;
    if (t < 132){
        int dx = t / 12, dy = t % 12;
        wsT[t] = (dy < 11) ? wAll[layer*121 + dy*11 + dx] : 0.f;
    }
    int x0 = bx*32 - 5, y0 = by*64 - 5;
    const float* inb = in + (size_t)bz*LA*CD;
    const int*   amb = aminoIdx ? aminoIdx + (size_t)bz*LA : nullptr;

    for (int g = wid; g < 19; g += 8){
        int row0 = g*4;
        float v[4];
        #pragma unroll
        for (int j=0;j<4;j++){
            int ly = row0 + j;
            int gy = y0 + ly, gx = x0 + lane;
            float val = 0.f;
            if (ly < 74 && gy >= 0 && gy < LA && gx >= 0 && gx < CD)
                val = amb ? E[(size_t)amb[gy]*CD + gx] : inb[(size_t)gy*CD + gx];
            v[j] = val;
        }
        *(float4*)&tileT[lane*84 + row0] = make_float4(v[0],v[1],v[2],v[3]);
        if (lane < 10){
            #pragma unroll
            for (int j=0;j<4;j++){
                int ly = row0 + j;
                int gy = y0 + ly, gx = x0 + 32 + lane;
                float val = 0.f;
                if (ly < 74 && gy >= 0 && gy < LA && gx >= 0 && gx < CD)
                    val = amb ? E[(size_t)amb[gy]*CD + gx] : inb[(size_t)gy*CD + gx];
                v[j] = val;
            }
            *(float4*)&tileT[(32+lane)*84 + row0] = make_float4(v[0],v[1],v[2],v[3]);
        }
    }
    __syncthreads();

    float bb = bAll[layer];
    float acc[8];
    #pragma unroll
    for (int q=0;q<8;q++) acc[q] = bb;
    #pragma unroll
    for (int dx=0; dx<11; dx++){
        float4 rv4[5];
        #pragma unroll
        for (int g=0;g<5;g++)
            rv4[g] = *(const float4*)&tileT[(tx+dx)*84 + ty*8 + g*4];
        const float* rv = (const float*)rv4;
        float4 w0 = *(const float4*)&wsT[dx*12];
        float4 w1 = *(const float4*)&wsT[dx*12 + 4];
        float4 w2 = *(const float4*)&wsT[dx*12 + 8];
        const float wv[12] = {w0.x,w0.y,w0.z,w0.w, w1.x,w1.y,w1.z,w1.w, w2.x,w2.y,w2.z,w2.w};
        #pragma unroll
        for (int dy=0; dy<11; dy++){
            #pragma unroll
            for (int q=0;q<8;q++) acc[q] += rv[q+dy]*wv[dy];
        }
    }
    float* ob = out + (size_t)bz*LA*CD + (size_t)(by*64 + ty*8)*CD + bx*32 + tx;
    #pragma unroll
    for (int q=0;q<8;q++){
        float v = fmaxf(acc[q], 0.f);
        ob[(size_t)q*CD] = roundOut ? round_tf32(v) : v;
    }
}

// ---------------- attention pool (tf32 mma) ----------------
__global__ __launch_bounds__(256) void k_pool(
    const float* __restrict__ vec, const float* __restrict__ mask,
    const float* __restrict__ ba, float* __restrict__ outAcc, int R)
{
    __shared__ uint32_t As[32*36];
    __shared__ uint32_t Bs[32*132];
    __shared__ float mks[32];
    int b = blockIdx.y;
    int r0tile = blockIdx.x*32;
    int t = threadIdx.x;
    int wid = t >> 5, lane = t & 31;
    int rbase = (wid & 1)*16, cbase = (wid >> 1)*32;
    int r0 = lane >> 2, c0 = lane & 3;

    if (t < 32) mks[t] = mask[(size_t)b*R + r0tile + t];

    float acc[4][4];
    #pragma unroll
    for (int nb=0;nb<4;nb++){ acc[nb][0]=0.f; acc[nb][1]=0.f; acc[nb][2]=0.f; acc[nb][3]=0.f; }

    for (int k0=0; k0<LATD; k0+=32){
        {
            int r = t >> 3;
            float4 v = *(const float4*)(vec + ((size_t)b*R + r0tile + r)*LATD + k0 + (t & 7)*4);
            *(float4*)&As[r*36 + (t & 7)*4] = v;
        }
        #pragma unroll
        for (int p=0;p<4;p++){
            int kr = (t >> 5) + p*8;
            float4 v = *(const float4*)(g_waT + (size_t)(k0+kr)*LATD + (t & 31)*4);
            *(float4*)&Bs[kr*132 + (t & 31)*4] = v;
        }
        __syncthreads();
        #pragma unroll
        for (int kk=0; kk<32; kk+=8){
            uint32_t a0 = As[(rbase+r0)*36   + kk + c0];
            uint32_t a1 = As[(rbase+r0+8)*36 + kk + c0];
            uint32_t a2 = As[(rbase+r0)*36   + kk + c0 + 4];
            uint32_t a3 = As[(rbase+r0+8)*36 + kk + c0 + 4];
            #pragma unroll
            for (int nb=0; nb<4; nb++){
                uint32_t b0 = Bs[(kk+c0)*132   + cbase + nb*8 + r0];
                uint32_t b1 = Bs[(kk+c0+4)*132 + cbase + nb*8 + r0];
                mma_tf32(acc[nb], a0, a1, a2, a3, b0, b1);
            }
        }
        __syncthreads();
    }

    float m0 = mks[rbase + r0], m1 = mks[rbase + r0 + 8];
    #pragma unroll
    for (int nb=0; nb<4; nb++){
        int col = cbase + nb*8 + 2*c0;
        float bb0 = ba[col], bb1 = ba[col+1];
        float cs0 = lrelu_f(acc[nb][0] + bb0)*m0 + lrelu_f(acc[nb][2] + bb0)*m1;
        float cs1 = lrelu_f(acc[nb][1] + bb1)*m0 + lrelu_f(acc[nb][3] + bb1)*m1;
        #pragma unroll
        for (int o=4; o<32; o<<=1){
            cs0 += __shfl_xor_sync(0xffffffffu, cs0, o);
            cs1 += __shfl_xor_sync(0xffffffffu, cs1, o);
        }
        if (r0 == 0){
            atomicAdd(&outAcc[(size_t)b*LATD + col],     cs0);
            atomicAdd(&outAcc[(size_t)b*LATD + col + 1], cs1);
        }
    }
}

// ---------------- final head ----------------
__global__ void k_final(const float* __restrict__ amask, const float* __restrict__ pmask,
                        const float* __restrict__ pw, const float* __restrict__ pb,
                        float* __restrict__ outp)
{
    int b = blockIdx.x, t = threadIdx.x;
    __shared__ float red[256];
    __shared__ float sums[2];
    float sa = 0.f;
    for (int i=t; i<NA; i+=256) sa += amask[(size_t)b*NA + i];
    red[t] = sa; __syncthreads();
    for (int o=128;o;o>>=1){ if (t<o) red[t] += red[t+o]; __syncthreads(); }
    if (t==0) sums[0] = red[0];
    __syncthreads();
    float sp = 0.f;
    for (int i=t; i<LA; i+=256) sp += pmask[(size_t)b*LA + i];
    red[t] = sp; __syncthreads();
    for (int o=128;o;o>>=1){ if (t<o) red[t] += red[t+o]; __syncthreads(); }
    if (t==0) sums[1] = red[0];
    __syncthreads();
    float v = (t < LATD) ? g_comp[(size_t)b*LATD + t] / sums[0]
                         : g_prot[(size_t)b*LATD + (t-LATD)] / sums[1];
    v = lrelu_f(lrelu_f(v));
    red[t] = v * pw[t]; __syncthreads();
    for (int o=128;o;o>>=1){ if (t<o) red[t] += red[t+o]; __syncthreads(); }
    if (t==0) outp[b] = red[0] + pb[0];
}

// ---------------- launch (2-stream fork/join) ----------------
extern "C" void kernel_launch(void* const* d_in, const int* in_sizes, int n_in,
                              void* d_out, int out_size)
{
    const int*   atoms      = (const int*)  d_in[0];
    const float* atoms_mask = (const float*)d_in[1];
    const int*   adjacency  = (const int*)  d_in[2];
    const int*   amino      = (const int*)  d_in[3];
    const float* amino_mask = (const float*)d_in[4];
    const float* E_atom     = (const float*)d_in[5];
    const float* E_amino    = (const float*)d_in[6];
    const float* W_gat      = (const float*)d_in[7];
    const float* a_gat      = (const float*)d_in[8];
    const float* W_go       = (const float*)d_in[9];
    const float* a_go       = (const float*)d_in[10];
    const float* W_comp_w   = (const float*)d_in[11];
    const float* W_comp_b   = (const float*)d_in[12];
    const float* conv_w     = (const float*)d_in[13];
    const float* conv_b     = (const float*)d_in[14];
    const float* W_att_w    = (const float*)d_in[15];
    const float* W_att_b    = (const float*)d_in[16];
    const float* pred_w     = (const float*)d_in[17];
    const float* pred_b     = (const float*)d_in[18];
    float* outp = (float*)d_out;

    float *p_wcat, *p_wgo, *p_eat, *p_wh, *p_src1, *p_dst1, *p_multi, *p_wh2, *p_src2, *p_dst2;
    float *p_x, *p_wcT, *p_avec, *p_pv0, *p_pv1, *p_comp, *p_prot;
    cudaGetSymbolAddress((void**)&p_wcat,  g_wcat);
    cudaGetSymbolAddress((void**)&p_wgo,   g_wgo);
    cudaGetSymbolAddress((void**)&p_eat,   g_eat);
    cudaGetSymbolAddress((void**)&p_wh,    g_wh);
    cudaGetSymbolAddress((void**)&p_src1,  g_src1);
    cudaGetSymbolAddress((void**)&p_dst1,  g_dst1);
    cudaGetSymbolAddress((void**)&p_multi, g_multi);
    cudaGetSymbolAddress((void**)&p_wh2,   g_wh2);
    cudaGetSymbolAddress((void**)&p_src2,  g_src2);
    cudaGetSymbolAddress((void**)&p_dst2,  g_dst2);
    cudaGetSymbolAddress((void**)&p_x,     g_x);
    cudaGetSymbolAddress((void**)&p_wcT,   g_wcT);
    cudaGetSymbolAddress((void**)&p_avec,  g_avec);
    cudaGetSymbolAddress((void**)&p_pv0,   g_pv0);
    cudaGetSymbolAddress((void**)&p_pv1,   g_pv1);
    cudaGetSymbolAddress((void**)&p_comp,  g_comp);
    cudaGetSymbolAddress((void**)&p_prot,  g_prot);

    const int SM1 = (64*36 + 32*(GD+4) + NA + 64) * 4;   // 23808 B
    const int SM2 = (32*36 + 32*(CD+4) + NA + 32) * 4;   // 23680 B

    static cudaStream_t s2 = nullptr;
    static cudaEvent_t evFork = nullptr, evAdj = nullptr, evJoin = nullptr;
    if (!s2){
        cudaStreamCreateWithFlags(&s2, cudaStreamNonBlocking);
        cudaEventCreateWithFlags(&evFork, cudaEventDisableTiming);
        cudaEventCreateWithFlags(&evAdj,  cudaEventDisableTiming);
        cudaEventCreateWithFlags(&evJoin, cudaEventDisableTiming);
    }

    // ---- fork FIRST: side stream is independent of k_pack ----
    cudaEventRecord(evFork, 0);
    cudaStreamWaitEvent(s2, evFork, 0);

    // ---- side stream: adjacency bitmask, then amino path ----
    k_adjbits<<<BN*NA/256, 256, 0, s2>>>(adjacency);
    cudaEventRecord(evAdj, s2);
    k_conv<<<dim3(4,16,BB), dim3(32,8), 0, s2>>>(p_pv1, p_pv0, conv_w, conv_b, 0, amino, E_amino, 0);
    k_conv<<<dim3(4,16,BB), dim3(32,8), 0, s2>>>(p_pv0, p_pv1, conv_w, conv_b, 1, nullptr, nullptr, 0);
    k_conv<<<dim3(4,16,BB), dim3(32,8), 0, s2>>>(p_pv1, p_pv0, conv_w, conv_b, 2, nullptr, nullptr, 1);
    k_pool<<<dim3(LA/32, BB), 256, 0, s2>>>(p_pv0, amino_mask, W_att_b, p_prot, LA);
    cudaEventRecord(evJoin, s2);

    // ---- atom path on main stream ----
    k_pack<<<128, 256>>>(W_gat, W_comp_w, W_att_w, W_go, E_atom);
    k_gemm<<<dim3(4,128), 256>>>(p_eat, p_wcat, p_wh, NH*GD, CD, nullptr, 0, atoms, a_gat, 1);
    cudaStreamWaitEvent(0, evAdj, 0);
    k_attn1<<<dim3(NA/64, BB, NH), 256, SM1>>>(p_wh, p_src1, p_dst1, p_multi);
    k_gemm<<<dim3(2,128), 256>>>(p_multi, p_wgo, p_wh2, CD, NH*GD, nullptr, 0, nullptr, a_go, 2);
    k_attn2<<<dim3(NA/32, BB), 256, SM2>>>(p_wh2, p_src2, p_dst2, p_x);
    k_gemm<<<dim3(2,128), 256>>>(p_x, p_wcT, p_avec, LATD, CD, W_comp_b, 1, nullptr, nullptr, 0);
    k_pool<<<dim3(NA/32, BB), 256>>>(p_avec, atoms_mask, W_att_b, p_comp, NA);

    // ---- join + head ----
    cudaStreamWaitEvent(0, evJoin, 0);
    k_final<<<BB, 256>>>(atoms_mask, amino_mask, pred_w, pred_b, outp);
}